// round 2
// baseline (speedup 1.0000x reference)
#include <cuda_runtime.h>
#include <cstdint>

#define D 128
#define MAX_N    150016   // n_src + n_out (deg array)
#define MAX_OUT  50048
#define MAX_E    500000

// ---- device scratch (static: no runtime allocation allowed) ----
__device__ float g_deg[MAX_N];
__device__ int   g_cnt[MAX_OUT];
__device__ int   g_off[MAX_OUT + 1];
__device__ int   g_cursor[MAX_OUT];
__device__ int   g_erow[MAX_E];
__device__ float g_ecoef[MAX_E];
__device__ float g_agg[(size_t)MAX_OUT * D];

// ---------------------------------------------------------------
// K0: init deg (self-loop weight 1 for every node) and zero counts
// ---------------------------------------------------------------
__global__ void init_kernel(int n_tot, int n_out) {
    int i = blockIdx.x * blockDim.x + threadIdx.x;
    if (i < n_tot) g_deg[i] = 1.0f;
    if (i < n_out) g_cnt[i] = 0;
}

// ---------------------------------------------------------------
// K1: degree accumulation (scattered over row) + dest histogram
//     edge_index is int32 (JAX x64 disabled downcasts int64->int32)
// ---------------------------------------------------------------
__global__ void degcnt_kernel(const int* __restrict__ ei,
                              const float* __restrict__ ew, int n_edge,
                              int n_tot, int n_out) {
    int e = blockIdx.x * blockDim.x + threadIdx.x;
    if (e >= n_edge) return;
    int row = ei[e];
    int col = ei[e + n_edge];
    if ((unsigned)row < (unsigned)n_tot) atomicAdd(&g_deg[row], ew[e]);
    if ((unsigned)col < (unsigned)n_out) atomicAdd(&g_cnt[col], 1);
}

// ---------------------------------------------------------------
// K2: single-block exclusive scan over counts (shuffle-based)
// ---------------------------------------------------------------
__global__ void scan_kernel(int n) {
    __shared__ int wsum[32];
    __shared__ int carry_s;
    int t = threadIdx.x, lane = t & 31, wid = t >> 5;
    if (t == 0) carry_s = 0;
    __syncthreads();
    for (int base = 0; base < n; base += 1024) {
        int i = base + t;
        int v = (i < n) ? g_cnt[i] : 0;
        int incl = v;
        #pragma unroll
        for (int o = 1; o < 32; o <<= 1) {
            int s = __shfl_up_sync(0xffffffffu, incl, o);
            if (lane >= o) incl += s;
        }
        if (lane == 31) wsum[wid] = incl;
        __syncthreads();
        if (wid == 0) {
            int ws = wsum[lane];
            int winc = ws;
            #pragma unroll
            for (int o = 1; o < 32; o <<= 1) {
                int s = __shfl_up_sync(0xffffffffu, winc, o);
                if (lane >= o) winc += s;
            }
            wsum[lane] = winc - ws;   // exclusive warp offsets
        }
        __syncthreads();
        int excl = carry_s + wsum[wid] + incl - v;
        if (i < n) { g_off[i] = excl; g_cursor[i] = excl; }
        __syncthreads();
        if (t == 1023) carry_s += wsum[31] + incl;
        __syncthreads();
    }
    if (threadIdx.x == 0) g_off[n] = carry_s;
}

// ---------------------------------------------------------------
// K3: place edges into CSR slots, folding normalization into coef
//      coef = w_e * rsqrt(deg[row_e]);  dinv[col] == 1 always
// ---------------------------------------------------------------
__global__ void scatter_kernel(const int* __restrict__ ei,
                               const float* __restrict__ ew, int n_edge,
                               int n_tot, int n_out) {
    int e = blockIdx.x * blockDim.x + threadIdx.x;
    if (e >= n_edge) return;
    int row = ei[e];
    int col = ei[e + n_edge];
    if ((unsigned)row >= (unsigned)n_tot || (unsigned)col >= (unsigned)n_out)
        return;
    float c = ew[e] * rsqrtf(g_deg[row]);
    int p = atomicAdd(&g_cursor[col], 1);
    g_erow[p]  = row;
    g_ecoef[p] = c;
}

// ---------------------------------------------------------------
// K4: per-destination gather in input space (one warp per node)
//      agg[j,:] = sum_e coef_e * x[row_e,:]
// ---------------------------------------------------------------
__global__ void gather_kernel(const float* __restrict__ x, int n_out) {
    int w = (blockIdx.x * blockDim.x + threadIdx.x) >> 5;
    int lane = threadIdx.x & 31;
    if (w >= n_out) return;
    int s = g_off[w], e = g_off[w + 1];
    const float4* x4 = (const float4*)x;
    float4 acc = make_float4(0.f, 0.f, 0.f, 0.f);
    for (int i = s; i < e; i++) {
        int   r = g_erow[i];
        float c = g_ecoef[i];
        float4 xv = x4[(size_t)r * 32 + lane];
        acc.x += c * xv.x; acc.y += c * xv.y;
        acc.z += c * xv.z; acc.w += c * xv.w;
    }
    ((float4*)g_agg)[(size_t)w * 32 + lane] = acc;
}

// ---------------------------------------------------------------
// K5: out = relu(agg @ W + b), M=n_out, K=N=128, fp32 SIMT GEMM
//     64-row tiles, 256 threads, 8x4 register tile per thread
// ---------------------------------------------------------------
__global__ __launch_bounds__(256) void gemm_kernel(const float* __restrict__ Wm,
                                                   const float* __restrict__ b,
                                                   float* __restrict__ out,
                                                   int n_rows) {
    __shared__ float As[64][32];
    __shared__ float Ws[32][128];
    float acc[8][4] = {};
    int row0 = blockIdx.x * 64;
    int tid = threadIdx.x;
    int ty = tid >> 5, lane = tid & 31;

    for (int kt = 0; kt < 4; kt++) {
        #pragma unroll
        for (int i = 0; i < 2; i++) {          // 64x32 A tile, float4 loads
            int lin4 = tid + i * 256;          // 0..511
            int r = lin4 >> 3, k4 = lin4 & 7;
            float4 v = make_float4(0.f, 0.f, 0.f, 0.f);
            if (row0 + r < n_rows)
                v = *(const float4*)&g_agg[(size_t)(row0 + r) * D + kt * 32 + k4 * 4];
            *(float4*)&As[r][k4 * 4] = v;
        }
        #pragma unroll
        for (int i = 0; i < 4; i++) {          // 32x128 W tile
            int lin4 = tid + i * 256;          // 0..1023
            int k = lin4 >> 5, c4 = lin4 & 31;
            *(float4*)&Ws[k][c4 * 4] =
                *(const float4*)&Wm[(size_t)(kt * 32 + k) * D + c4 * 4];
        }
        __syncthreads();
        #pragma unroll
        for (int k = 0; k < 32; k++) {
            float4 wv = *(const float4*)&Ws[k][lane * 4];
            #pragma unroll
            for (int i = 0; i < 8; i++) {
                float a = As[ty * 8 + i][k];
                acc[i][0] += a * wv.x;
                acc[i][1] += a * wv.y;
                acc[i][2] += a * wv.z;
                acc[i][3] += a * wv.w;
            }
        }
        __syncthreads();
    }

    float4 bv = *(const float4*)&b[lane * 4];
    #pragma unroll
    for (int i = 0; i < 8; i++) {
        int r = row0 + ty * 8 + i;
        if (r < n_rows) {
            float4 o;
            o.x = fmaxf(acc[i][0] + bv.x, 0.f);
            o.y = fmaxf(acc[i][1] + bv.y, 0.f);
            o.z = fmaxf(acc[i][2] + bv.z, 0.f);
            o.w = fmaxf(acc[i][3] + bv.w, 0.f);
            *(float4*)&out[(size_t)r * D + lane * 4] = o;
        }
    }
}

// ---------------------------------------------------------------
extern "C" void kernel_launch(void* const* d_in, const int* in_sizes, int n_in,
                              void* d_out, int out_size) {
    const float* x  = (const float*)d_in[0];   // [n_src, 128]
    const int*   ei = (const int*)d_in[1];     // [2, n_edge] int32 (JAX x64 off)
    const float* ew = (const float*)d_in[2];   // [n_edge]
    const float* Wm = (const float*)d_in[3];   // [128, 128]
    const float* b  = (const float*)d_in[4];   // [128]
    float* out = (float*)d_out;                // [n_out, 128]

    int n_src  = in_sizes[0] / D;
    int n_edge = in_sizes[2];
    int n_out  = out_size / D;
    int n_tot  = n_src + n_out;

    init_kernel<<<(n_tot + 255) / 256, 256>>>(n_tot, n_out);
    degcnt_kernel<<<(n_edge + 255) / 256, 256>>>(ei, ew, n_edge, n_tot, n_out);
    scan_kernel<<<1, 1024>>>(n_out);
    scatter_kernel<<<(n_edge + 255) / 256, 256>>>(ei, ew, n_edge, n_tot, n_out);
    gather_kernel<<<(n_out + 7) / 8, 256>>>(x, n_out);
    gemm_kernel<<<(n_out + 63) / 64, 256>>>(Wm, b, out, n_out);
}